// round 4
// baseline (speedup 1.0000x reference)
#include <cuda_runtime.h>
#include <math.h>

// Shapes (fixed)
#define B_  8
#define L_  1024
#define E_  512
#define H_  8
#define D_  64
#define BH_ 64
#define M_  8192   // B*L

// Scratch (__device__ globals; no runtime alloc)
__device__ float g_h [M_ * E_];            // layernorm out [m, e]
__device__ float g_q [BH_ * L_ * D_];      // [bh, l, d]
__device__ float g_k [BH_ * L_ * D_];      // (pre-scaled by D^-0.5)
__device__ float g_v [BH_ * L_ * D_];
__device__ float g_S [67108864];           // scores/probs [bh, l, m]
__device__ float g_R [67108864];           // rel logits    [bh, l, r]
__device__ float g_ao[BH_ * L_ * D_];      // attn out [bh, l, d]

// ------------------------------------------------------------- cp.async utils
__device__ __forceinline__ void cp_async4(void* smem, const void* gmem) {
    unsigned s = (unsigned)__cvta_generic_to_shared(smem);
    asm volatile("cp.async.ca.shared.global [%0], [%1], 4;\n" :: "r"(s), "l"(gmem));
}
__device__ __forceinline__ void cp_async16(void* smem, const void* gmem) {
    unsigned s = (unsigned)__cvta_generic_to_shared(smem);
    asm volatile("cp.async.cg.shared.global [%0], [%1], 16;\n" :: "r"(s), "l"(gmem));
}
__device__ __forceinline__ void cp_commit() { asm volatile("cp.async.commit_group;\n"); }
template<int N>
__device__ __forceinline__ void cp_wait() { asm volatile("cp.async.wait_group %0;\n" :: "n"(N)); }

// ---------------------------------------------------------------- LayerNorm
__global__ __launch_bounds__(128) void ln_kernel(const float* __restrict__ x,
                                                 const float* __restrict__ gamma,
                                                 const float* __restrict__ beta) {
    int row = blockIdx.x;
    const float* xr = x + (size_t)row * E_;
    float* hr = g_h + (size_t)row * E_;
    int t = threadIdx.x;
    float v[4];
    float s = 0.f, sq = 0.f;
#pragma unroll
    for (int i = 0; i < 4; i++) {
        v[i] = xr[t + 128 * i];
        s += v[i];
        sq += v[i] * v[i];
    }
    __shared__ float sh[8];
#pragma unroll
    for (int o = 16; o > 0; o >>= 1) {
        s  += __shfl_xor_sync(0xffffffffu, s, o);
        sq += __shfl_xor_sync(0xffffffffu, sq, o);
    }
    int w = t >> 5;
    if ((t & 31) == 0) { sh[w] = s; sh[4 + w] = sq; }
    __syncthreads();
    if (t == 0) {
        float S  = sh[0] + sh[1] + sh[2] + sh[3];
        float SQ = sh[4] + sh[5] + sh[6] + sh[7];
        float mu  = S / 512.f;
        float var = SQ / 512.f - mu * mu;
        sh[0] = mu;
        sh[1] = rsqrtf(var + 1e-5f);
    }
    __syncthreads();
    float mu = sh[0], rs = sh[1];
#pragma unroll
    for (int i = 0; i < 4; i++) {
        int c = t + 128 * i;
        hr[c] = (v[i] - mu) * rs * gamma[c] + beta[c];
    }
}

// Shared compute fragment: one 16-deep K chunk, 128x128 tile, 8x8/thread.
#define GEMM_CHUNK(AS, BS, ACC, TX, TY)                                   \
    _Pragma("unroll")                                                      \
    for (int kk = 0; kk < 16; kk++) {                                      \
        float a_[8];                                                       \
        _Pragma("unroll")                                                  \
        for (int i = 0; i < 8; i++) a_[i] = AS[kk][(TY) * 8 + i];          \
        float4 b0_ = *(const float4*)&BS[kk][(TX) * 8];                    \
        float4 b1_ = *(const float4*)&BS[kk][(TX) * 8 + 4];                \
        float b_[8] = {b0_.x, b0_.y, b0_.z, b0_.w, b1_.x, b1_.y, b1_.z, b1_.w}; \
        _Pragma("unroll")                                                  \
        for (int i = 0; i < 8; i++)                                        \
            _Pragma("unroll")                                              \
            for (int j = 0; j < 8; j++) ACC[i][j] += a_[i] * b_[j];        \
    }

// ------------------------------------------------- QKV projection (big GEMM)
__global__ __launch_bounds__(256) void qkv_kernel(const float* __restrict__ Wq,
                                                  const float* __restrict__ bq,
                                                  const float* __restrict__ Wk,
                                                  const float* __restrict__ bk,
                                                  const float* __restrict__ Wv,
                                                  const float* __restrict__ bv) {
    __shared__ float As[2][16][132];
    __shared__ float Bs[2][16][132];
    int n0g = blockIdx.x * 128;          // 0..1535
    int m0  = blockIdx.y * 128;
    int which = n0g >> 9;                // 0=q 1=k 2=v
    int nin = n0g & 511;
    const float* W    = (which == 0) ? Wq : (which == 1) ? Wk : Wv;
    const float* bias = (which == 0) ? bq : (which == 1) ? bk : bv;
    float* out        = (which == 0) ? g_q : (which == 1) ? g_k : g_v;
    float scale = (which == 1) ? 0.125f : 1.0f;

    int tid = threadIdx.x;
    int tx = tid & 15, ty = tid >> 4;
    float acc[8][8] = {};

    auto load = [&](int buf, int k0) {
#pragma unroll
        for (int it = 0; it < 8; it++) {
            int idx = tid + it * 256;
            int r = idx >> 4, c = idx & 15;
            cp_async4(&As[buf][c][r], &g_h[(size_t)(m0 + r) * E_ + k0 + c]);
            cp_async4(&Bs[buf][c][r], &W[(size_t)(nin + r) * E_ + k0 + c]);
        }
        cp_commit();
    };

    load(0, 0);
    for (int ch = 0; ch < 32; ch++) {
        int buf = ch & 1;
        if (ch < 31) { load(buf ^ 1, (ch + 1) * 16); cp_wait<1>(); }
        else cp_wait<0>();
        __syncthreads();
        GEMM_CHUNK(As[buf], Bs[buf], acc, tx, ty)
        __syncthreads();
    }
#pragma unroll
    for (int i = 0; i < 8; i++) {
        int m = m0 + ty * 8 + i;
        int bb = m >> 10, l = m & 1023;
#pragma unroll
        for (int j = 0; j < 8; j++) {
            int n = nin + tx * 8 + j;
            int hh = n >> 6, d = n & 63;
            out[(size_t)((bb * 8 + hh) * 1024 + l) * 64 + d] =
                (acc[i][j] + bias[n]) * scale;
        }
    }
}

// ---------------------------------------------------- S = Q K^T (k scaled)
__global__ __launch_bounds__(256) void qk_kernel() {
    int mi = blockIdx.x, li = blockIdx.y;
    if (mi > li) return;
    int m0 = mi * 128, l0 = li * 128, bh = blockIdx.z;
    __shared__ float As[2][16][132];
    __shared__ float Bs[2][16][132];
    const float* qb = g_q + (size_t)bh * 65536;
    const float* kb = g_k + (size_t)bh * 65536;
    int tid = threadIdx.x, tx = tid & 15, ty = tid >> 4;
    float acc[8][8] = {};

    auto load = [&](int buf, int k0) {
#pragma unroll
        for (int it = 0; it < 8; it++) {
            int idx = tid + it * 256;
            int r = idx >> 4, c = idx & 15;
            cp_async4(&As[buf][c][r], &qb[(size_t)(l0 + r) * 64 + k0 + c]);
            cp_async4(&Bs[buf][c][r], &kb[(size_t)(m0 + r) * 64 + k0 + c]);
        }
        cp_commit();
    };

    load(0, 0);
    for (int ch = 0; ch < 4; ch++) {
        int buf = ch & 1;
        if (ch < 3) { load(buf ^ 1, (ch + 1) * 16); cp_wait<1>(); }
        else cp_wait<0>();
        __syncthreads();
        GEMM_CHUNK(As[buf], Bs[buf], acc, tx, ty)
        __syncthreads();
    }
    float* Sb = g_S + ((size_t)bh << 20);
#pragma unroll
    for (int i = 0; i < 8; i++) {
        float* rowp = &Sb[(size_t)(l0 + ty * 8 + i) * 1024 + m0 + tx * 8];
        *(float4*)rowp       = make_float4(acc[i][0], acc[i][1], acc[i][2], acc[i][3]);
        *(float4*)(rowp + 4) = make_float4(acc[i][4], acc[i][5], acc[i][6], acc[i][7]);
    }
}

// ---------------------------------------- R[l,r] = q_l . Er[h, r, :]  (GEMM)
__global__ __launch_bounds__(256) void qer_kernel(const float* __restrict__ Er) {
    int ri = blockIdx.x, li = blockIdx.y;
    if (ri + li < 7) return;
    int r0 = ri * 128, l0 = li * 128, bh = blockIdx.z;
    int hh = bh & 7;
    __shared__ float As[2][16][132];
    __shared__ float Bs[2][16][132];
    const float* qb = g_q + (size_t)bh * 65536;
    const float* eb = Er + (size_t)hh * 65536;
    int tid = threadIdx.x, tx = tid & 15, ty = tid >> 4;
    float acc[8][8] = {};

    auto load = [&](int buf, int k0) {
#pragma unroll
        for (int it = 0; it < 8; it++) {
            int idx = tid + it * 256;
            int r = idx >> 4, c = idx & 15;
            cp_async4(&As[buf][c][r], &qb[(size_t)(l0 + r) * 64 + k0 + c]);
            cp_async4(&Bs[buf][c][r], &eb[(size_t)(r0 + r) * 64 + k0 + c]);
        }
        cp_commit();
    };

    load(0, 0);
    for (int ch = 0; ch < 4; ch++) {
        int buf = ch & 1;
        if (ch < 3) { load(buf ^ 1, (ch + 1) * 16); cp_wait<1>(); }
        else cp_wait<0>();
        __syncthreads();
        GEMM_CHUNK(As[buf], Bs[buf], acc, tx, ty)
        __syncthreads();
    }
    float* Rb = g_R + ((size_t)bh << 20);
#pragma unroll
    for (int i = 0; i < 8; i++) {
        float* rowp = &Rb[(size_t)(l0 + ty * 8 + i) * 1024 + r0 + tx * 8];
        *(float4*)rowp       = make_float4(acc[i][0], acc[i][1], acc[i][2], acc[i][3]);
        *(float4*)(rowp + 4) = make_float4(acc[i][4], acc[i][5], acc[i][6], acc[i][7]);
    }
}

// --------------------------- causal softmax with fused rel gather-add
__global__ __launch_bounds__(128) void softmax_kernel() {
    int l = blockIdx.x, bh = blockIdx.y;
    float* row        = g_S + ((size_t)bh << 20) + ((size_t)l << 10);
    const float* rrow = g_R + ((size_t)bh << 20) + ((size_t)l << 10) + (1023 - l);
    int n = l + 1;
    int t = threadIdx.x;
    float vals[8];
    int cnt = 0;
    float mx = -1e30f;
    for (int i = t; i < n; i += 128) {
        float v = row[i] + rrow[i];
        vals[cnt++] = v;
        mx = fmaxf(mx, v);
    }
    __shared__ float shm[4], shs[4], bc[1];
#pragma unroll
    for (int o = 16; o > 0; o >>= 1) mx = fmaxf(mx, __shfl_xor_sync(0xffffffffu, mx, o));
    if ((t & 31) == 0) shm[t >> 5] = mx;
    __syncthreads();
    float MX = fmaxf(fmaxf(shm[0], shm[1]), fmaxf(shm[2], shm[3]));
    float sum = 0.f;
    for (int j = 0; j < cnt; j++) {
        vals[j] = __expf(vals[j] - MX);
        sum += vals[j];
    }
#pragma unroll
    for (int o = 16; o > 0; o >>= 1) sum += __shfl_xor_sync(0xffffffffu, sum, o);
    if ((t & 31) == 0) shs[t >> 5] = sum;
    __syncthreads();
    if (t == 0) bc[0] = 1.f / (shs[0] + shs[1] + shs[2] + shs[3]);
    __syncthreads();
    float inv = bc[0];
    cnt = 0;
    for (int i = t; i < n; i += 128) row[i] = vals[cnt++] * inv;
}

// --------------------------------------------------------------- out = P @ V
// Tile 128(l) x 64(d), 128 threads, 8x8 per thread, K-chunks of 16, pipelined.
__global__ __launch_bounds__(128) void pv_kernel() {
    int li = blockIdx.x, bh = blockIdx.y;
    int l0 = li * 128;
    __shared__ float Ps[2][16][132];
    __shared__ float Vs[2][16][68];
    const float* Sb = g_S + ((size_t)bh << 20);
    const float* vb = g_v + (size_t)bh * 65536;
    int tid = threadIdx.x, tx = tid & 7, ty = tid >> 3;   // 8 x 16
    float acc[8][8] = {};
    int NC = (li + 1) * 8;                // 16-wide chunks

    auto load = [&](int buf, int cc) {
        int kbase = cc * 16;
        if (kbase + 16 <= l0) {           // fully below diagonal: unmasked
#pragma unroll
            for (int it = 0; it < 16; it++) {
                int kk = it;
                cp_async4(&Ps[buf][kk][tid],
                          &Sb[(size_t)(l0 + tid) * 1024 + kbase + kk]);
            }
        } else {                          // diagonal tile: mask m > l
#pragma unroll
            for (int it = 0; it < 16; it++) {
                int kk = it;
                int mg = kbase + kk, lg = l0 + tid;
                if (mg <= lg)
                    cp_async4(&Ps[buf][kk][tid],
                              &Sb[(size_t)lg * 1024 + mg]);
                else
                    Ps[buf][kk][tid] = 0.f;
            }
        }
#pragma unroll
        for (int it = 0; it < 2; it++) {
            int f = tid + it * 128;       // float4 index, 256 total
            int rr = f >> 4, c4 = (f & 15) * 4;
            cp_async16(&Vs[buf][rr][c4], &vb[(size_t)(kbase + rr) * 64 + c4]);
        }
        cp_commit();
    };

    load(0, 0);
    for (int cc = 0; cc < NC; cc++) {
        int buf = cc & 1;
        if (cc < NC - 1) { load(buf ^ 1, cc + 1); cp_wait<1>(); }
        else cp_wait<0>();
        __syncthreads();
#pragma unroll
        for (int kk = 0; kk < 16; kk++) {
            float a[8];
#pragma unroll
            for (int i = 0; i < 8; i++) a[i] = Ps[buf][kk][ty * 8 + i];
            float4 b0 = *(const float4*)&Vs[buf][kk][tx * 8];
            float4 b1 = *(const float4*)&Vs[buf][kk][tx * 8 + 4];
            float b[8] = {b0.x, b0.y, b0.z, b0.w, b1.x, b1.y, b1.z, b1.w};
#pragma unroll
            for (int i = 0; i < 8; i++)
#pragma unroll
                for (int j = 0; j < 8; j++) acc[i][j] += a[i] * b[j];
        }
        __syncthreads();
    }
    float* ob = g_ao + (size_t)bh * 65536;
#pragma unroll
    for (int i = 0; i < 8; i++) {
        float* rowp = &ob[(size_t)(l0 + ty * 8 + i) * 64 + tx * 8];
        *(float4*)rowp       = make_float4(acc[i][0], acc[i][1], acc[i][2], acc[i][3]);
        *(float4*)(rowp + 4) = make_float4(acc[i][4], acc[i][5], acc[i][6], acc[i][7]);
    }
}

// -------------------------------------------------- output projection + bias
__global__ __launch_bounds__(256) void oproj_kernel(const float* __restrict__ Wo,
                                                    const float* __restrict__ bo,
                                                    float* __restrict__ out) {
    __shared__ float As[2][16][132];
    __shared__ float Bs[2][16][132];
    int n0 = blockIdx.x * 128;
    int m0 = blockIdx.y * 128;
    int tid = threadIdx.x, tx = tid & 15, ty = tid >> 4;
    float acc[8][8] = {};

    auto load = [&](int buf, int k0) {
#pragma unroll
        for (int it = 0; it < 8; it++) {
            int idx = tid + it * 256;
            int r = idx >> 4, c = idx & 15;
            int m = m0 + r, e = k0 + c;
            cp_async4(&As[buf][c][r],
                      &g_ao[(size_t)(((m >> 10) * 8 + (e >> 6)) * 1024 + (m & 1023)) * 64 + (e & 63)]);
            cp_async4(&Bs[buf][c][r], &Wo[(size_t)(n0 + r) * E_ + e]);
        }
        cp_commit();
    };

    load(0, 0);
    for (int ch = 0; ch < 32; ch++) {
        int buf = ch & 1;
        if (ch < 31) { load(buf ^ 1, (ch + 1) * 16); cp_wait<1>(); }
        else cp_wait<0>();
        __syncthreads();
        GEMM_CHUNK(As[buf], Bs[buf], acc, tx, ty)
        __syncthreads();
    }
#pragma unroll
    for (int i = 0; i < 8; i++) {
        int m = m0 + ty * 8 + i;
#pragma unroll
        for (int j = 0; j < 8; j++) {
            int n = n0 + tx * 8 + j;
            out[(size_t)m * 512 + n] = acc[i][j] + bo[n];
        }
    }
}

// ----------------------------------------------------------------- launcher
extern "C" void kernel_launch(void* const* d_in, const int* in_sizes, int n_in,
                              void* d_out, int out_size) {
    const float* x     = (const float*)d_in[0];
    const float* gamma = (const float*)d_in[2];
    const float* beta  = (const float*)d_in[3];
    const float* Wq    = (const float*)d_in[4];
    const float* bq    = (const float*)d_in[5];
    const float* Wk    = (const float*)d_in[6];
    const float* bk    = (const float*)d_in[7];
    const float* Wv    = (const float*)d_in[8];
    const float* bv    = (const float*)d_in[9];
    const float* Wo    = (const float*)d_in[10];
    const float* bo    = (const float*)d_in[11];
    const float* Er    = (const float*)d_in[12];
    float* out = (float*)d_out;

    ln_kernel<<<M_, 128>>>(x, gamma, beta);
    qkv_kernel<<<dim3(12, 64), 256>>>(Wq, bq, Wk, bk, Wv, bv);
    qk_kernel<<<dim3(8, 8, BH_), 256>>>();
    qer_kernel<<<dim3(8, 8, BH_), 256>>>(Er);
    softmax_kernel<<<dim3(L_, BH_), 128>>>();
    pv_kernel<<<dim3(8, BH_), 128>>>();
    oproj_kernel<<<dim3(4, 64), 256>>>(Wo, bo, out);
}

// round 6
// speedup vs baseline: 1.7300x; 1.7300x over previous
#include <cuda_runtime.h>
#include <math.h>
#include <stdint.h>

// Shapes (fixed)
#define B_  8
#define L_  1024
#define E_  512
#define H_  8
#define D_  64
#define BH_ 64
#define M_  8192   // B*L

// Scratch (__device__ globals; no runtime alloc)
__device__ float g_h [M_ * E_];            // layernorm out [m, e]
__device__ float g_q [BH_ * L_ * D_];      // [bh, l, d]
__device__ float g_k [BH_ * L_ * D_];      // (pre-scaled by D^-0.5)
__device__ float g_v [BH_ * L_ * D_];
__device__ float g_S [67108864];           // scores/probs [bh, l, m]
__device__ float g_R [67108864];           // rel logits   [bh, l, r]
__device__ float g_ao[BH_ * L_ * D_];      // attn out [bh, l, d]

// --------------------------------------------------------------- mma helpers
__device__ __forceinline__ uint32_t f2t(float x) {
    uint32_t r;
    asm("cvt.rna.tf32.f32 %0, %1;" : "=r"(r) : "f"(x));
    return r;
}
__device__ __forceinline__ void mma8(float* d, const uint32_t* a,
                                     uint32_t b0, uint32_t b1) {
    asm volatile(
        "mma.sync.aligned.m16n8k8.row.col.f32.tf32.tf32.f32 "
        "{%0,%1,%2,%3}, {%4,%5,%6,%7}, {%8,%9}, {%0,%1,%2,%3};"
        : "+f"(d[0]), "+f"(d[1]), "+f"(d[2]), "+f"(d[3])
        : "r"(a[0]), "r"(a[1]), "r"(a[2]), "r"(a[3]), "r"(b0), "r"(b1));
}

// ---------------------------------------------------------------- LayerNorm
__global__ __launch_bounds__(128) void ln_kernel(const float* __restrict__ x,
                                                 const float* __restrict__ gamma,
                                                 const float* __restrict__ beta) {
    int row = blockIdx.x;
    const float* xr = x + (size_t)row * E_;
    float* hr = g_h + (size_t)row * E_;
    int t = threadIdx.x;
    float v[4];
    float s = 0.f, sq = 0.f;
#pragma unroll
    for (int i = 0; i < 4; i++) {
        v[i] = xr[t + 128 * i];
        s += v[i];
        sq += v[i] * v[i];
    }
    __shared__ float sh[8];
#pragma unroll
    for (int o = 16; o > 0; o >>= 1) {
        s  += __shfl_xor_sync(0xffffffffu, s, o);
        sq += __shfl_xor_sync(0xffffffffu, sq, o);
    }
    int w = t >> 5;
    if ((t & 31) == 0) { sh[w] = s; sh[4 + w] = sq; }
    __syncthreads();
    if (t == 0) {
        float S  = sh[0] + sh[1] + sh[2] + sh[3];
        float SQ = sh[4] + sh[5] + sh[6] + sh[7];
        float mu  = S / 512.f;
        float var = SQ / 512.f - mu * mu;
        sh[0] = mu;
        sh[1] = rsqrtf(var + 1e-5f);
    }
    __syncthreads();
    float mu = sh[0], rs = sh[1];
#pragma unroll
    for (int i = 0; i < 4; i++) {
        int c = t + 128 * i;
        hr[c] = (v[i] - mu) * rs * gamma[c] + beta[c];
    }
}

// ------------------------------------------------- QKV projection (tf32 mma)
// 128x128 tile, 8 warps (4m x 2n), warp = 32m x 64n, mma m16n8k8.
__global__ __launch_bounds__(256) void qkv_kernel(const float* __restrict__ Wq,
                                                  const float* __restrict__ bq,
                                                  const float* __restrict__ Wk,
                                                  const float* __restrict__ bk,
                                                  const float* __restrict__ Wv,
                                                  const float* __restrict__ bv) {
    __shared__ float As[16][132];
    __shared__ float Bs[16][132];
    int n0g = blockIdx.x * 128;
    int m0  = blockIdx.y * 128;
    int which = n0g >> 9;
    int nin = n0g & 511;
    const float* W    = (which == 0) ? Wq : (which == 1) ? Wk : Wv;
    const float* bias = (which == 0) ? bq : (which == 1) ? bk : bv;
    float* out        = (which == 0) ? g_q : (which == 1) ? g_k : g_v;
    float scale = (which == 1) ? 0.125f : 1.0f;

    int tid = threadIdx.x;
    int lane = tid & 31, warp = tid >> 5;
    int g = lane >> 2, tig = lane & 3;
    int wm = warp & 3, wn = warp >> 2;
    int fr = tid & 127, kh = tid >> 7;        // fill: row, k-half

    float acc[2][8][4] = {};
    float4 ra[2], rb[2];

    auto ldg = [&](int k0) {
        const float* ap = &g_h[(size_t)(m0 + fr) * E_ + k0 + kh * 8];
        const float* bp = &W[(size_t)(nin + fr) * E_ + k0 + kh * 8];
        ra[0] = *(const float4*)ap;  ra[1] = *(const float4*)(ap + 4);
        rb[0] = *(const float4*)bp;  rb[1] = *(const float4*)(bp + 4);
    };
    auto sts = [&]() {
#pragma unroll
        for (int j = 0; j < 4; j++) {
            As[kh * 8 + j][fr]     = ((float*)&ra[0])[j];
            As[kh * 8 + 4 + j][fr] = ((float*)&ra[1])[j];
            Bs[kh * 8 + j][fr]     = ((float*)&rb[0])[j];
            Bs[kh * 8 + 4 + j][fr] = ((float*)&rb[1])[j];
        }
    };

    ldg(0); sts(); __syncthreads();
    for (int ch = 0; ch < 32; ch++) {
        if (ch < 31) ldg((ch + 1) * 16);
#pragma unroll
        for (int ks = 0; ks < 2; ks++) {
            int k = ks * 8;
            uint32_t ua[2][4];
#pragma unroll
            for (int mi = 0; mi < 2; mi++) {
                int rb_ = wm * 32 + mi * 16;
                ua[mi][0] = f2t(As[k + tig][rb_ + g]);
                ua[mi][1] = f2t(As[k + tig][rb_ + g + 8]);
                ua[mi][2] = f2t(As[k + 4 + tig][rb_ + g]);
                ua[mi][3] = f2t(As[k + 4 + tig][rb_ + g + 8]);
            }
#pragma unroll
            for (int ni = 0; ni < 8; ni++) {
                int cb = wn * 64 + ni * 8 + g;
                uint32_t b0 = f2t(Bs[k + tig][cb]);
                uint32_t b1 = f2t(Bs[k + 4 + tig][cb]);
                mma8(acc[0][ni], ua[0], b0, b1);
                mma8(acc[1][ni], ua[1], b0, b1);
            }
        }
        __syncthreads();
        if (ch < 31) { sts(); __syncthreads(); }
    }
#pragma unroll
    for (int mi = 0; mi < 2; mi++) {
        int r0 = m0 + wm * 32 + mi * 16 + g;
#pragma unroll
        for (int ni = 0; ni < 8; ni++) {
            int c = nin + wn * 64 + ni * 8 + tig * 2;
            int hh = c >> 6, d = c & 63;
            float b0v = bias[c], b1v = bias[c + 1];
            float* a = acc[mi][ni];
            int m1 = r0, m2 = r0 + 8;
            float2 v0 = make_float2((a[0] + b0v) * scale, (a[1] + b1v) * scale);
            float2 v1 = make_float2((a[2] + b0v) * scale, (a[3] + b1v) * scale);
            *(float2*)&out[(size_t)(((m1 >> 10) * 8 + hh) * 1024 + (m1 & 1023)) * 64 + d] = v0;
            *(float2*)&out[(size_t)(((m2 >> 10) * 8 + hh) * 1024 + (m2 & 1023)) * 64 + d] = v1;
        }
    }
}

// --------------------------- generic 128x128 K=64 split-tf32 mma core (S/R)
// 3xTF32: fp32-quality logits (feeds exp).
__device__ __forceinline__ void qk_core(const float* __restrict__ Arows,
                                        const float* __restrict__ Brows,
                                        float* __restrict__ Out,
                                        int l0, int m0) {
    __shared__ float As[16][132];
    __shared__ float Bs[16][132];
    int tid = threadIdx.x;
    int lane = tid & 31, warp = tid >> 5;
    int g = lane >> 2, tig = lane & 3;
    int wm = warp & 3, wn = warp >> 2;
    int fr = tid & 127, kh = tid >> 7;

    float acc[2][8][4] = {};
    float4 ra[2], rb[2];
    auto ldg = [&](int k0) {
        const float* ap = &Arows[(size_t)(l0 + fr) * 64 + k0 + kh * 8];
        const float* bp = &Brows[(size_t)(m0 + fr) * 64 + k0 + kh * 8];
        ra[0] = *(const float4*)ap;  ra[1] = *(const float4*)(ap + 4);
        rb[0] = *(const float4*)bp;  rb[1] = *(const float4*)(bp + 4);
    };
    auto sts = [&]() {
#pragma unroll
        for (int j = 0; j < 4; j++) {
            As[kh * 8 + j][fr]     = ((float*)&ra[0])[j];
            As[kh * 8 + 4 + j][fr] = ((float*)&ra[1])[j];
            Bs[kh * 8 + j][fr]     = ((float*)&rb[0])[j];
            Bs[kh * 8 + 4 + j][fr] = ((float*)&rb[1])[j];
        }
    };

    ldg(0); sts(); __syncthreads();
    for (int ch = 0; ch < 4; ch++) {
        if (ch < 3) ldg((ch + 1) * 16);
#pragma unroll
        for (int ks = 0; ks < 2; ks++) {
            int k = ks * 8;
            uint32_t ah[2][4], al[2][4];
#pragma unroll
            for (int mi = 0; mi < 2; mi++) {
                int rb_ = wm * 32 + mi * 16;
                float f0 = As[k + tig][rb_ + g];
                float f1 = As[k + tig][rb_ + g + 8];
                float f2 = As[k + 4 + tig][rb_ + g];
                float f3 = As[k + 4 + tig][rb_ + g + 8];
                ah[mi][0] = f2t(f0); al[mi][0] = f2t(f0 - __uint_as_float(ah[mi][0]));
                ah[mi][1] = f2t(f1); al[mi][1] = f2t(f1 - __uint_as_float(ah[mi][1]));
                ah[mi][2] = f2t(f2); al[mi][2] = f2t(f2 - __uint_as_float(ah[mi][2]));
                ah[mi][3] = f2t(f3); al[mi][3] = f2t(f3 - __uint_as_float(ah[mi][3]));
            }
#pragma unroll
            for (int ni = 0; ni < 8; ni++) {
                int cb = wn * 64 + ni * 8 + g;
                float fb0 = Bs[k + tig][cb];
                float fb1 = Bs[k + 4 + tig][cb];
                uint32_t bh0 = f2t(fb0), bh1 = f2t(fb1);
                uint32_t bl0 = f2t(fb0 - __uint_as_float(bh0));
                uint32_t bl1 = f2t(fb1 - __uint_as_float(bh1));
#pragma unroll
                for (int mi = 0; mi < 2; mi++) {
                    mma8(acc[mi][ni], al[mi], bh0, bh1);
                    mma8(acc[mi][ni], ah[mi], bl0, bl1);
                    mma8(acc[mi][ni], ah[mi], bh0, bh1);
                }
            }
        }
        __syncthreads();
        if (ch < 3) { sts(); __syncthreads(); }
    }
#pragma unroll
    for (int mi = 0; mi < 2; mi++) {
        int lr = l0 + wm * 32 + mi * 16 + g;
#pragma unroll
        for (int ni = 0; ni < 8; ni++) {
            int mc = m0 + wn * 64 + ni * 8 + 2 * tig;
            float* a = acc[mi][ni];
            *(float2*)&Out[(size_t)lr * 1024 + mc]       = make_float2(a[0], a[1]);
            *(float2*)&Out[(size_t)(lr + 8) * 1024 + mc] = make_float2(a[2], a[3]);
        }
    }
}

__global__ __launch_bounds__(256) void qk_kernel() {
    int mi = blockIdx.x, li = blockIdx.y;
    if (mi > li) return;
    int bh = blockIdx.z;
    qk_core(g_q + (size_t)bh * 65536, g_k + (size_t)bh * 65536,
            g_S + ((size_t)bh << 20), li * 128, mi * 128);
}

__global__ __launch_bounds__(256) void qer_kernel(const float* __restrict__ Er) {
    int ri = blockIdx.x, li = blockIdx.y;
    if (ri + li < 7) return;
    int bh = blockIdx.z;
    qk_core(g_q + (size_t)bh * 65536, Er + (size_t)(bh & 7) * 65536,
            g_R + ((size_t)bh << 20), li * 128, ri * 128);
}

// --------------------------- causal softmax with fused rel gather-add
__global__ __launch_bounds__(128) void softmax_kernel() {
    int l = blockIdx.x, bh = blockIdx.y;
    float* row        = g_S + ((size_t)bh << 20) + ((size_t)l << 10);
    const float* rrow = g_R + ((size_t)bh << 20) + ((size_t)l << 10) + (1023 - l);
    int n = l + 1;
    int t = threadIdx.x;
    float vals[8];
    int cnt = 0;
    float mx = -1e30f;
    for (int i = t; i < n; i += 128) {
        float v = row[i] + rrow[i];
        vals[cnt++] = v;
        mx = fmaxf(mx, v);
    }
    __shared__ float shm[4], shs[4], bc[1];
#pragma unroll
    for (int o = 16; o > 0; o >>= 1) mx = fmaxf(mx, __shfl_xor_sync(0xffffffffu, mx, o));
    if ((t & 31) == 0) shm[t >> 5] = mx;
    __syncthreads();
    float MX = fmaxf(fmaxf(shm[0], shm[1]), fmaxf(shm[2], shm[3]));
    float sum = 0.f;
    for (int j = 0; j < cnt; j++) {
        vals[j] = __expf(vals[j] - MX);
        sum += vals[j];
    }
#pragma unroll
    for (int o = 16; o > 0; o >>= 1) sum += __shfl_xor_sync(0xffffffffu, sum, o);
    if ((t & 31) == 0) shs[t >> 5] = sum;
    __syncthreads();
    if (t == 0) bc[0] = 1.f / (shs[0] + shs[1] + shs[2] + shs[3]);
    __syncthreads();
    float inv = bc[0];
    cnt = 0;
    for (int i = t; i < n; i += 128) row[i] = vals[cnt++] * inv;
}

// --------------------------------------------------------------- out = P @ V
// 128(l) x 64(d), 8 warps (4m x 2n), warp 32m x 32n, tf32 mma.
__global__ __launch_bounds__(256) void pv_kernel() {
    int li = blockIdx.x, bh = blockIdx.y;
    int l0 = li * 128;
    __shared__ float Ps[16][132];
    __shared__ float Vs[16][68];
    const float* Sb = g_S + ((size_t)bh << 20);
    const float* vb = g_v + (size_t)bh * 65536;
    int tid = threadIdx.x;
    int lane = tid & 31, warp = tid >> 5;
    int g = lane >> 2, tig = lane & 3;
    int wm = warp & 3, wn = warp >> 2;
    int fr = tid & 127, kh = tid >> 7;
    int vkk = tid >> 4, vc4 = (tid & 15) * 4;

    float acc[2][4][4] = {};
    float4 rp[2], rv;
    int NC = (li + 1) * 8;

    auto ldg = [&](int cc) {
        int kbase = cc * 16;
        const float* sp = &Sb[(size_t)(l0 + fr) * 1024 + kbase + kh * 8];
        rp[0] = *(const float4*)sp;  rp[1] = *(const float4*)(sp + 4);
        rv = *(const float4*)&vb[(size_t)(kbase + vkk) * 64 + vc4];
    };
    auto sts = [&](int cc) {
        int kbase = cc * 16;
        int lg = l0 + fr;
#pragma unroll
        for (int j = 0; j < 4; j++) {
            int m0j = kbase + kh * 8 + j;
            int m1j = m0j + 4;
            Ps[kh * 8 + j][fr]     = (m0j <= lg) ? ((float*)&rp[0])[j] : 0.f;
            Ps[kh * 8 + 4 + j][fr] = (m1j <= lg) ? ((float*)&rp[1])[j] : 0.f;
        }
        *(float4*)&Vs[vkk][vc4] = rv;
    };

    ldg(0); sts(0); __syncthreads();
    for (int cc = 0; cc < NC; cc++) {
        if (cc < NC - 1) ldg(cc + 1);
#pragma unroll
        for (int ks = 0; ks < 2; ks++) {
            int k = ks * 8;
            uint32_t ua[2][4];
#pragma unroll
            for (int mi = 0; mi < 2; mi++) {
                int rb_ = wm * 32 + mi * 16;
                ua[mi][0] = f2t(Ps[k + tig][rb_ + g]);
                ua[mi][1] = f2t(Ps[k + tig][rb_ + g + 8]);
                ua[mi][2] = f2t(Ps[k + 4 + tig][rb_ + g]);
                ua[mi][3] = f2t(Ps[k + 4 + tig][rb_ + g + 8]);
            }
#pragma unroll
            for (int ni = 0; ni < 4; ni++) {
                int cb = wn * 32 + ni * 8 + g;
                uint32_t b0 = f2t(Vs[k + tig][cb]);
                uint32_t b1 = f2t(Vs[k + 4 + tig][cb]);
                mma8(acc[0][ni], ua[0], b0, b1);
                mma8(acc[1][ni], ua[1], b0, b1);
            }
        }
        __syncthreads();
        if (cc < NC - 1) { sts(cc + 1); __syncthreads(); }
    }
    float* ob = g_ao + (size_t)bh * 65536;
#pragma unroll
    for (int mi = 0; mi < 2; mi++) {
        int row = l0 + wm * 32 + mi * 16 + g;
#pragma unroll
        for (int ni = 0; ni < 4; ni++) {
            int col = wn * 32 + ni * 8 + 2 * tig;
            float* a = acc[mi][ni];
            *(float2*)&ob[(size_t)row * 64 + col]       = make_float2(a[0], a[1]);
            *(float2*)&ob[(size_t)(row + 8) * 64 + col] = make_float2(a[2], a[3]);
        }
    }
}

// -------------------------------------------------- output projection + bias
__global__ __launch_bounds__(256) void oproj_kernel(const float* __restrict__ Wo,
                                                    const float* __restrict__ bo,
                                                    float* __restrict__ out) {
    __shared__ float As[16][132];
    __shared__ float Bs[16][132];
    int n0 = blockIdx.x * 128;
    int m0 = blockIdx.y * 128;
    int tid = threadIdx.x;
    int lane = tid & 31, warp = tid >> 5;
    int g = lane >> 2, tig = lane & 3;
    int wm = warp & 3, wn = warp >> 2;
    int fr = tid & 127, kh = tid >> 7;

    float acc[2][8][4] = {};
    float4 ra[2], rb[2];
    auto ldg = [&](int k0) {
        int m = m0 + fr;
        int e = k0 + kh * 8;
        const float* ap = &g_ao[(size_t)(((m >> 10) * 8 + (e >> 6)) * 1024 + (m & 1023)) * 64 + (e & 63)];
        const float* bp = &Wo[(size_t)(n0 + fr) * E_ + e];
        ra[0] = *(const float4*)ap;  ra[1] = *(const float4*)(ap + 4);
        rb[0] = *(const float4*)bp;  rb[1] = *(const float4*)(bp + 4);
    };
    auto sts = [&]() {
#pragma unroll
        for (int j = 0; j < 4; j++) {
            As[kh * 8 + j][fr]     = ((float*)&ra[0])[j];
            As[kh * 8 + 4 + j][fr] = ((float*)&ra[1])[j];
            Bs[kh * 8 + j][fr]     = ((float*)&rb[0])[j];
            Bs[kh * 8 + 4 + j][fr] = ((float*)&rb[1])[j];
        }
    };

    ldg(0); sts(); __syncthreads();
    for (int ch = 0; ch < 32; ch++) {
        if (ch < 31) ldg((ch + 1) * 16);
#pragma unroll
        for (int ks = 0; ks < 2; ks++) {
            int k = ks * 8;
            uint32_t ua[2][4];
#pragma unroll
            for (int mi = 0; mi < 2; mi++) {
                int rb_ = wm * 32 + mi * 16;
                ua[mi][0] = f2t(As[k + tig][rb_ + g]);
                ua[mi][1] = f2t(As[k + tig][rb_ + g + 8]);
                ua[mi][2] = f2t(As[k + 4 + tig][rb_ + g]);
                ua[mi][3] = f2t(As[k + 4 + tig][rb_ + g + 8]);
            }
#pragma unroll
            for (int ni = 0; ni < 8; ni++) {
                int cb = wn * 64 + ni * 8 + g;
                uint32_t b0 = f2t(Bs[k + tig][cb]);
                uint32_t b1 = f2t(Bs[k + 4 + tig][cb]);
                mma8(acc[0][ni], ua[0], b0, b1);
                mma8(acc[1][ni], ua[1], b0, b1);
            }
        }
        __syncthreads();
        if (ch < 31) { sts(); __syncthreads(); }
    }
#pragma unroll
    for (int mi = 0; mi < 2; mi++) {
        int r0 = m0 + wm * 32 + mi * 16 + g;
#pragma unroll
        for (int ni = 0; ni < 8; ni++) {
            int c = n0 + wn * 64 + ni * 8 + 2 * tig;
            float b0v = bo[c], b1v = bo[c + 1];
            float* a = acc[mi][ni];
            *(float2*)&out[(size_t)r0 * 512 + c]       = make_float2(a[0] + b0v, a[1] + b1v);
            *(float2*)&out[(size_t)(r0 + 8) * 512 + c] = make_float2(a[2] + b0v, a[3] + b1v);
        }
    }
}

// ----------------------------------------------------------------- launcher
extern "C" void kernel_launch(void* const* d_in, const int* in_sizes, int n_in,
                              void* d_out, int out_size) {
    const float* x     = (const float*)d_in[0];
    const float* gamma = (const float*)d_in[2];
    const float* beta  = (const float*)d_in[3];
    const float* Wq    = (const float*)d_in[4];
    const float* bq    = (const float*)d_in[5];
    const float* Wk    = (const float*)d_in[6];
    const float* bk    = (const float*)d_in[7];
    const float* Wv    = (const float*)d_in[8];
    const float* bv    = (const float*)d_in[9];
    const float* Wo    = (const float*)d_in[10];
    const float* bo    = (const float*)d_in[11];
    const float* Er    = (const float*)d_in[12];
    float* out = (float*)d_out;

    ln_kernel<<<M_, 128>>>(x, gamma, beta);
    qkv_kernel<<<dim3(12, 64), 256>>>(Wq, bq, Wk, bk, Wv, bv);
    qk_kernel<<<dim3(8, 8, BH_), 256>>>();
    qer_kernel<<<dim3(8, 8, BH_), 256>>>(Er);
    softmax_kernel<<<dim3(L_, BH_), 128>>>();
    pv_kernel<<<dim3(8, BH_), 256>>>();
    oproj_kernel<<<dim3(4, 64), 256>>>(Wo, bo, out);
}